// round 4
// baseline (speedup 1.0000x reference)
#include <cuda_runtime.h>
#include <cuda_bf16.h>

// PLIF spiking neuron: mem = mem*sigmoid(tau[c]) + x[t]; spike = (mem-1)>0;
// mem = (1-spike)*mem.  x: [B=32, T=8, C=128, H=32, W=32] f32, tau: [C] f32.
// Pure HBM stream (268 MB logical). R2 measured 37.1us kernel = 7.24 TB/s
// effective (~90% of spec). R3: 2x float4 per thread (MLP_p1=16), streaming
// cache hints (__ldcs/__stcs) since there is zero reuse.

#define PLIF_T    8
#define PLIF_HW   1024                     // 32*32   = 2^10
#define PLIF_CHW  131072                   // 128*HW  = 2^17

__global__ __launch_bounds__(256) void PLIF_73538430042799_kernel(
    const float* __restrict__ x,
    const float* __restrict__ tau,
    float* __restrict__ out,
    int n_threads)                          // B*CHW/8 = 524,288
{
    int tid = blockIdx.x * blockDim.x + threadIdx.x;
    if (tid >= n_threads) return;

    int i = tid << 3;                       // first of 8 consecutive elements
    int b = i >> 17;                        // i / CHW
    int r = i & (PLIF_CHW - 1);             // i % CHW
    int c = r >> 10;                        // channel = r / HW  (8 elems never
                                            // cross a channel: HW=1024, 8|1024)

    // sigmoid of per-channel leak. tau is 512 B -> L2-resident.
    float tau_s = 1.0f / (1.0f + expf(-__ldg(&tau[c])));

    size_t base = (size_t)b * (PLIF_T * PLIF_CHW) + (size_t)r;
    const float4* xp = reinterpret_cast<const float4*>(x + base);
    float4*       op = reinterpret_cast<float4*>(out + base);
    const int t_stride4 = PLIF_CHW / 4;     // float4 stride between timesteps

    // Front-batch all loads: 16 outstanding LDG.128 per thread (evict-first)
    float4 va[PLIF_T], vb[PLIF_T];
#pragma unroll
    for (int t = 0; t < PLIF_T; ++t) {
        va[t] = __ldcs(&xp[t * t_stride4]);
        vb[t] = __ldcs(&xp[t * t_stride4 + 1]);
    }

    float m0 = 0.f, m1 = 0.f, m2 = 0.f, m3 = 0.f;
    float n0 = 0.f, n1 = 0.f, n2 = 0.f, n3 = 0.f;

#pragma unroll
    for (int t = 0; t < PLIF_T; ++t) {
        m0 = m0 * tau_s + va[t].x;
        m1 = m1 * tau_s + va[t].y;
        m2 = m2 * tau_s + va[t].z;
        m3 = m3 * tau_s + va[t].w;
        n0 = n0 * tau_s + vb[t].x;
        n1 = n1 * tau_s + vb[t].y;
        n2 = n2 * tau_s + vb[t].z;
        n3 = n3 * tau_s + vb[t].w;

        float sa0 = (m0 - 1.0f) > 0.0f ? 1.0f : 0.0f;
        float sa1 = (m1 - 1.0f) > 0.0f ? 1.0f : 0.0f;
        float sa2 = (m2 - 1.0f) > 0.0f ? 1.0f : 0.0f;
        float sa3 = (m3 - 1.0f) > 0.0f ? 1.0f : 0.0f;
        float sb0 = (n0 - 1.0f) > 0.0f ? 1.0f : 0.0f;
        float sb1 = (n1 - 1.0f) > 0.0f ? 1.0f : 0.0f;
        float sb2 = (n2 - 1.0f) > 0.0f ? 1.0f : 0.0f;
        float sb3 = (n3 - 1.0f) > 0.0f ? 1.0f : 0.0f;

        // hard reset: spiked neurons zero their membrane
        m0 = sa0 > 0.f ? 0.f : m0;
        m1 = sa1 > 0.f ? 0.f : m1;
        m2 = sa2 > 0.f ? 0.f : m2;
        m3 = sa3 > 0.f ? 0.f : m3;
        n0 = sb0 > 0.f ? 0.f : n0;
        n1 = sb1 > 0.f ? 0.f : n1;
        n2 = sb2 > 0.f ? 0.f : n2;
        n3 = sb3 > 0.f ? 0.f : n3;

        float4 spa; spa.x = sa0; spa.y = sa1; spa.z = sa2; spa.w = sa3;
        float4 spb; spb.x = sb0; spb.y = sb1; spb.z = sb2; spb.w = sb3;
        __stcs(&op[t * t_stride4],     spa);
        __stcs(&op[t * t_stride4 + 1], spb);
    }
}

extern "C" void kernel_launch(void* const* d_in, const int* in_sizes, int n_in,
                              void* d_out, int out_size)
{
    const float* x   = (const float*)d_in[0];   // [B,T,C,H,W] f32
    const float* tau = (const float*)d_in[1];   // [C] f32
    float* out = (float*)d_out;

    int n_elems   = in_sizes[0];                 // 33,554,432
    int n_threads = n_elems / PLIF_T / 8;        // 524,288 (exact)

    int block = 256;
    int grid  = (n_threads + block - 1) / block; // 2048
    PLIF_73538430042799_kernel<<<grid, block>>>(x, tau, out, n_threads);
}

// round 16
// speedup vs baseline: 1.0472x; 1.0472x over previous
#include <cuda_runtime.h>
#include <cuda_bf16.h>

// PLIF spiking neuron: mem = mem*sigmoid(tau[c]) + x[t]; spike = (mem-1)>0;
// mem = (1-spike)*mem.  x: [B=32, T=8, C=128, H=32, W=32] f32, tau: [C] f32.
//
// R2 (this layout, no hints): 37.1us kernel, DRAM 72.9%, occ 79.6%. Effective
// logical throughput 7.24 TB/s (~90% of spec). R3 (2x float4 + __ldcs/__stcs)
// REGRESSED to 44.6us: occupancy collapsed to 30% and evict-first stores
// forced write-backs into the critical path. R5-R15 = R2 layout + __ldcs only:
// evict-first READS free L2 space so the write stream can linger in L2
// (R2 measured only ~214MB DRAM traffic of 268MB logical for this reason).

#define PLIF_T    8
#define PLIF_HW   1024                     // 32*32   = 2^10
#define PLIF_CHW  131072                   // 128*HW  = 2^17

__global__ __launch_bounds__(256) void PLIF_73538430042799_kernel(
    const float* __restrict__ x,
    const float* __restrict__ tau,
    float* __restrict__ out,
    int n_threads)                          // B*CHW/4 = 1,048,576
{
    int tid = blockIdx.x * blockDim.x + threadIdx.x;
    if (tid >= n_threads) return;

    int i = tid << 2;                       // element index within [0, B*CHW)
    int b = i >> 17;                        // i / CHW
    int r = i & (PLIF_CHW - 1);             // i % CHW
    int c = r >> 10;                        // channel = r / HW

    // sigmoid of per-channel leak. tau is 512 B -> L2/L1 resident.
    float tau_s = 1.0f / (1.0f + expf(-__ldg(&tau[c])));

    size_t base = (size_t)b * (PLIF_T * PLIF_CHW) + (size_t)r;
    const float4* xp = reinterpret_cast<const float4*>(x + base);
    float4*       op = reinterpret_cast<float4*>(out + base);
    const int t_stride4 = PLIF_CHW / 4;     // float4 stride between timesteps

    // Front-batch all T loads: 8 outstanding LDG.128 per thread, evict-first
    // (input is never re-read; keep L2 free for the write stream).
    float4 v[PLIF_T];
#pragma unroll
    for (int t = 0; t < PLIF_T; ++t)
        v[t] = __ldcs(&xp[t * t_stride4]);

    float m0 = 0.f, m1 = 0.f, m2 = 0.f, m3 = 0.f;

#pragma unroll
    for (int t = 0; t < PLIF_T; ++t) {
        m0 = m0 * tau_s + v[t].x;
        m1 = m1 * tau_s + v[t].y;
        m2 = m2 * tau_s + v[t].z;
        m3 = m3 * tau_s + v[t].w;

        float s0 = (m0 - 1.0f) > 0.0f ? 1.0f : 0.0f;
        float s1 = (m1 - 1.0f) > 0.0f ? 1.0f : 0.0f;
        float s2 = (m2 - 1.0f) > 0.0f ? 1.0f : 0.0f;
        float s3 = (m3 - 1.0f) > 0.0f ? 1.0f : 0.0f;

        // hard reset: spiked neurons zero their membrane
        m0 = s0 > 0.f ? 0.f : m0;
        m1 = s1 > 0.f ? 0.f : m1;
        m2 = s2 > 0.f ? 0.f : m2;
        m3 = s3 > 0.f ? 0.f : m3;

        float4 sp; sp.x = s0; sp.y = s1; sp.z = s2; sp.w = s3;
        op[t * t_stride4] = sp;             // default policy: let writes linger in L2
    }
}

extern "C" void kernel_launch(void* const* d_in, const int* in_sizes, int n_in,
                              void* d_out, int out_size)
{
    const float* x   = (const float*)d_in[0];   // [B,T,C,H,W] f32
    const float* tau = (const float*)d_in[1];   // [C] f32
    float* out = (float*)d_out;

    int n_elems   = in_sizes[0];                 // 33,554,432
    int n_threads = n_elems / PLIF_T / 4;        // 1,048,576 (exact)

    int block = 256;
    int grid  = (n_threads + block - 1) / block; // 4096
    PLIF_73538430042799_kernel<<<grid, block>>>(x, tau, out, n_threads);
}

// round 17
// speedup vs baseline: 1.0539x; 1.0064x over previous
#include <cuda_runtime.h>
#include <cuda_bf16.h>

// PLIF spiking neuron: mem = mem*sigmoid(tau[c]) + x[t]; spike = (mem-1)>0;
// mem = (1-spike)*mem.  x: [B=32, T=8, C=128, H=32, W=32] f32, tau: [C] f32.
//
// FINAL (R2 config, measured twice at the ceiling):
//   R2  (this kernel):       37.06us kernel / 45.31us harness, DRAM 72.9%,
//                            occ 79.6%, regs 32.
//   R16 (R2 + __ldcs reads): 37.09us kernel / 45.44us harness, occ 63.1%,
//                            regs 40 -> NEUTRAL. Cache policy + occupancy
//                            (63-80%) do not move time: hard BW ceiling.
//   R3  (2x float4 + __ldcs/__stcs): 44.6us REGRESSION (occ 30%, forced
//                            write-backs).
// Effective logical throughput 268 MB / 37.1us = 7.23 TB/s (~90% of 8 TB/s
// spec). Traffic is at the information-theoretic floor (read every input
// byte once, write every f32 spike once), so this is roofline-complete.
//
// Layout: one thread = 4 consecutive spatial positions (float4); all 8
// timesteps front-batched into registers (8 outstanding LDG.128, MLP_p1=8),
// recurrence entirely in registers, 8 STG.128.

#define PLIF_T    8
#define PLIF_HW   1024                     // 32*32   = 2^10
#define PLIF_CHW  131072                   // 128*HW  = 2^17

__global__ __launch_bounds__(256) void PLIF_73538430042799_kernel(
    const float* __restrict__ x,
    const float* __restrict__ tau,
    float* __restrict__ out,
    int n_threads)                          // B*CHW/4 = 1,048,576
{
    int tid = blockIdx.x * blockDim.x + threadIdx.x;
    if (tid >= n_threads) return;

    int i = tid << 2;                       // element index within [0, B*CHW)
    int b = i >> 17;                        // i / CHW
    int r = i & (PLIF_CHW - 1);             // i % CHW
    int c = r >> 10;                        // channel = r / HW

    // sigmoid of per-channel leak. tau is 512 B -> L2/L1 resident.
    float tau_s = 1.0f / (1.0f + expf(-__ldg(&tau[c])));

    size_t base = (size_t)b * (PLIF_T * PLIF_CHW) + (size_t)r;
    const float4* xp = reinterpret_cast<const float4*>(x + base);
    float4*       op = reinterpret_cast<float4*>(out + base);
    const int t_stride4 = PLIF_CHW / 4;     // float4 stride between timesteps

    // Front-batch all T loads -> 8 outstanding LDG.128 per thread
    float4 v[PLIF_T];
#pragma unroll
    for (int t = 0; t < PLIF_T; ++t)
        v[t] = xp[t * t_stride4];

    float m0 = 0.f, m1 = 0.f, m2 = 0.f, m3 = 0.f;

#pragma unroll
    for (int t = 0; t < PLIF_T; ++t) {
        m0 = m0 * tau_s + v[t].x;
        m1 = m1 * tau_s + v[t].y;
        m2 = m2 * tau_s + v[t].z;
        m3 = m3 * tau_s + v[t].w;

        float s0 = (m0 - 1.0f) > 0.0f ? 1.0f : 0.0f;
        float s1 = (m1 - 1.0f) > 0.0f ? 1.0f : 0.0f;
        float s2 = (m2 - 1.0f) > 0.0f ? 1.0f : 0.0f;
        float s3 = (m3 - 1.0f) > 0.0f ? 1.0f : 0.0f;

        // hard reset: spiked neurons zero their membrane
        m0 = s0 > 0.f ? 0.f : m0;
        m1 = s1 > 0.f ? 0.f : m1;
        m2 = s2 > 0.f ? 0.f : m2;
        m3 = s3 > 0.f ? 0.f : m3;

        float4 sp; sp.x = s0; sp.y = s1; sp.z = s2; sp.w = s3;
        op[t * t_stride4] = sp;             // default policy: writes linger in L2
    }
}

extern "C" void kernel_launch(void* const* d_in, const int* in_sizes, int n_in,
                              void* d_out, int out_size)
{
    const float* x   = (const float*)d_in[0];   // [B,T,C,H,W] f32
    const float* tau = (const float*)d_in[1];   // [C] f32
    float* out = (float*)d_out;

    int n_elems   = in_sizes[0];                 // 33,554,432
    int n_threads = n_elems / PLIF_T / 4;        // 1,048,576 (exact)

    int block = 256;
    int grid  = (n_threads + block - 1) / block; // 4096
    PLIF_73538430042799_kernel<<<grid, block>>>(x, tau, out, n_threads);
}